// round 12
// baseline (speedup 1.0000x reference)
#include <cuda_runtime.h>
#include <cuda_fp16.h>
#include <cstdint>

#define T_SEQ   2048
#define BATCH   2
#define DM      512
#define NROWS   (BATCH * T_SEQ)   // 4096
#define QKV_N   (3 * DM)          // 1536
#define WIN     32
#define WW      (2 * WIN - 1)     // 63

// ---------------- scratch (__device__ globals: allocation-free rule) -------
__device__ __half g_qkvh[NROWS * QKV_N];     // fp16 q|k|v
__device__ __half g_xh[NROWS * DM];          // fp16 x
__device__ __half g_wqh[QKV_N * DM];         // fp16 w_qkv
__device__ __half g_wph[DM * DM];            // fp16 w_proj
__device__ __half g_ah[NROWS * DM];          // fp16 attention output

// ---------------- helpers ---------------------------------------------------
__device__ __forceinline__ uint32_t smem_u32(const void* p) {
    uint32_t a;
    asm("{ .reg .u64 t; cvta.to.shared.u64 t, %1; cvt.u32.u64 %0, t; }"
        : "=r"(a) : "l"(p));
    return a;
}

__device__ __forceinline__ void mma_fp16(float* c, const uint32_t* a, const uint32_t* b) {
    asm volatile(
        "mma.sync.aligned.m16n8k16.row.col.f32.f16.f16.f32 "
        "{%0,%1,%2,%3}, {%4,%5,%6,%7}, {%8,%9}, {%0,%1,%2,%3};"
        : "+f"(c[0]), "+f"(c[1]), "+f"(c[2]), "+f"(c[3])
        : "r"(a[0]), "r"(a[1]), "r"(a[2]), "r"(a[3]), "r"(b[0]), "r"(b[1]));
}

__device__ __forceinline__ void ldm_x4(uint32_t* d, uint32_t addr) {
    asm volatile("ldmatrix.sync.aligned.m8n8.x4.shared.b16 {%0,%1,%2,%3}, [%4];"
                 : "=r"(d[0]), "=r"(d[1]), "=r"(d[2]), "=r"(d[3]) : "r"(addr));
}
__device__ __forceinline__ void ldm_x2(uint32_t* d, uint32_t addr) {
    asm volatile("ldmatrix.sync.aligned.m8n8.x2.shared.b16 {%0,%1}, [%2];"
                 : "=r"(d[0]), "=r"(d[1]) : "r"(addr));
}
__device__ __forceinline__ void ldm_x2_t(uint32_t* d, uint32_t addr) {
    asm volatile("ldmatrix.sync.aligned.m8n8.x2.trans.shared.b16 {%0,%1}, [%2];"
                 : "=r"(d[0]), "=r"(d[1]) : "r"(addr));
}

// ---------------- GEMM smem geometry: K-chunk 64 ----------------------------
#define ROWB    144

// ---------------------------------------------------------------------------
// fused fp32 -> fp16 convert for 3 arrays (one launch)
// ---------------------------------------------------------------------------
__global__ __launch_bounds__(256) void conv_fp16_3(
    const float4* __restrict__ s0, __half* __restrict__ d0, int n0,
    const float4* __restrict__ s1, __half* __restrict__ d1, int n1,
    const float4* __restrict__ s2, __half* __restrict__ d2, int n2)
{
    int i = blockIdx.x * blockDim.x + threadIdx.x;
    const float4* s; __half* d; int off;
    if (i < n0)           { s = s0; d = d0; off = i; }
    else if (i < n0 + n1) { s = s1; d = d1; off = i - n0; }
    else if (i < n0 + n1 + n2) { s = s2; d = d2; off = i - n0 - n1; }
    else return;
    float4 v = s[off];
    __half2 lo = __floats2half2_rn(v.x, v.y);
    __half2 hi = __floats2half2_rn(v.z, v.w);
    uint2 r;
    r.x = *reinterpret_cast<uint32_t*>(&lo);
    r.y = *reinterpret_cast<uint32_t*>(&hi);
    reinterpret_cast<uint2*>(d)[off] = r;
}

// ---------------------------------------------------------------------------
// fp16 HMMA GEMM: C[M,Ntot] = A[M,K] @ B[Ntot,K]^T + bias (fp32 accum)
// CTA tile BM x 128, 8 warps x (BM/2 x 32), K-chunk 64, cp.async dbl buffer.
// B fragments via ldmatrix.x4 (2 n-tiles per instruction).
// ---------------------------------------------------------------------------
template<int BM, int HALF_OUT>
__global__ __launch_bounds__(256, 2) void gemm_fp16(
    int Ntot, int kchunks,
    const __half* __restrict__ A, const __half* __restrict__ B,
    const float* __restrict__ bias, void* __restrict__ Cv)
{
    constexpr int MT = BM / 32;              // m-subtiles (16 rows) per warp
    constexpr int TILEB_A = BM * ROWB;
    constexpr int TILEB_B = 128 * ROWB;
    constexpr int STAGEB  = TILEB_A + TILEB_B;

    extern __shared__ __align__(16) char smem[];
    const uint32_t sbase = smem_u32(smem);

    const int tid    = threadIdx.x;
    const int wid    = tid >> 5;
    const int lane   = tid & 31;
    const int l4     = lane >> 2;
    const int lq     = lane & 3;
    const int warp_m = (wid & 1) * (BM / 2);
    const int warp_n = (wid >> 1) * 32;
    const int m0     = blockIdx.y * BM;
    const int n0     = blockIdx.x * 128;
    const int K      = kchunks * 64;

    const int g8 = lane >> 3;
    const int r8 = lane & 7;
    const uint32_t a_off  = (uint32_t)((warp_m + (g8 & 1) * 8 + r8) * ROWB + (g8 >> 1) * 16);
    // B x4: lanes 0-7/(8-15): n-tile0 rows @ k0/k8; 16-23/(24-31): n-tile1.
    const uint32_t b_off4 = (uint32_t)((warp_n + (g8 >> 1) * 8 + r8) * ROWB + (g8 & 1) * 16);

    auto issue_stage = [&](int c, int buf) {
#pragma unroll
        for (int j = 0; j < BM / 32; j++) {
            const int idx = tid + 256 * j;
            const int row = idx >> 3;
            const int c16 = idx & 7;
            const __half* gp = A + (size_t)(m0 + row) * K + c * 64 + c16 * 8;
            const uint32_t sa = sbase + buf * STAGEB + row * ROWB + c16 * 16;
            asm volatile("cp.async.cg.shared.global [%0], [%1], 16;"
                         :: "r"(sa), "l"(gp) : "memory");
        }
#pragma unroll
        for (int j = 0; j < 4; j++) {
            const int idx = tid + 256 * j;
            const int row = idx >> 3;
            const int c16 = idx & 7;
            const __half* gp = B + (size_t)(n0 + row) * K + c * 64 + c16 * 8;
            const uint32_t sa = sbase + buf * STAGEB + TILEB_A + row * ROWB + c16 * 16;
            asm volatile("cp.async.cg.shared.global [%0], [%1], 16;"
                         :: "r"(sa), "l"(gp) : "memory");
        }
        asm volatile("cp.async.commit_group;" ::: "memory");
    };

    float acc[MT][4][4];
#pragma unroll
    for (int i = 0; i < MT; i++)
#pragma unroll
        for (int j = 0; j < 4; j++)
#pragma unroll
            for (int r = 0; r < 4; r++) acc[i][j][r] = 0.0f;

    issue_stage(0, 0);
    if (kchunks > 1) issue_stage(1, 1);

    for (int c = 0; c < kchunks; c++) {
        const int buf = c & 1;
        if (c + 1 < kchunks) asm volatile("cp.async.wait_group 1;" ::: "memory");
        else                 asm volatile("cp.async.wait_group 0;" ::: "memory");
        __syncthreads();

        const uint32_t Ab = sbase + buf * STAGEB;
        const uint32_t Bb = Ab + TILEB_A;

#pragma unroll
        for (int kk = 0; kk < 4; kk++) {
            uint32_t a[MT][4];
#pragma unroll
            for (int mt = 0; mt < MT; mt++)
                ldm_x4(a[mt], Ab + a_off + mt * 16 * ROWB + kk * 32);
#pragma unroll
            for (int np = 0; np < 2; np++) {
                uint32_t b4[4];
                ldm_x4(b4, Bb + b_off4 + np * 16 * ROWB + kk * 32);
#pragma unroll
                for (int mt = 0; mt < MT; mt++)
                    mma_fp16(acc[mt][np * 2 + 0], a[mt], b4 + 0);
#pragma unroll
                for (int mt = 0; mt < MT; mt++)
                    mma_fp16(acc[mt][np * 2 + 1], a[mt], b4 + 2);
            }
        }

        __syncthreads();
        if (c + 2 < kchunks) issue_stage(c + 2, buf);
    }

    // ---- epilogue: bias add, fp32 or fp16 out ----
#pragma unroll
    for (int nt = 0; nt < 4; nt++) {
        const int col = n0 + warp_n + nt * 8 + 2 * lq;
        const float2 bv = *reinterpret_cast<const float2*>(bias + col);
#pragma unroll
        for (int mt = 0; mt < MT; mt++) {
            const int row = m0 + warp_m + mt * 16 + l4;
            float2 r0, r1;
            r0.x = acc[mt][nt][0] + bv.x;
            r0.y = acc[mt][nt][1] + bv.y;
            r1.x = acc[mt][nt][2] + bv.x;
            r1.y = acc[mt][nt][3] + bv.y;
            if (HALF_OUT) {
                __half* C = (__half*)Cv;
                __half2 h0 = __floats2half2_rn(r0.x, r0.y);
                __half2 h1 = __floats2half2_rn(r1.x, r1.y);
                *reinterpret_cast<uint32_t*>(C + (size_t)row * Ntot + col) =
                    *reinterpret_cast<uint32_t*>(&h0);
                *reinterpret_cast<uint32_t*>(C + (size_t)(row + 8) * Ntot + col) =
                    *reinterpret_cast<uint32_t*>(&h1);
            } else {
                float* C = (float*)Cv;
                *reinterpret_cast<float2*>(C + (size_t)row * Ntot + col) = r0;
                *reinterpret_cast<float2*>(C + (size_t)(row + 8) * Ntot + col) = r1;
            }
        }
    }
}

#define GEMM_SMEM_128 (2 * (128 * ROWB + 128 * ROWB))   // 73728
#define GEMM_SMEM_64  (2 * (64  * ROWB + 128 * ROWB))   // 55296

// ---------------------------------------------------------------------------
// Tensor-core local attention (unchanged from R10).
// ---------------------------------------------------------------------------
#define TQ     32
#define SPAN   96
#define JOFF   32
#define ROW2   272
#define P_ROW  208
#define SM_Q   0
#define SM_K   8704
#define SM_RM  34816
#define SM_RS  35328
#define ATTN_SMEM 35840

__global__ __launch_bounds__(256) void attn_mma(
    const __half* __restrict__ qkv, __half* __restrict__ oh)
{
    extern __shared__ __align__(16) char smem[];
    const uint32_t sb = smem_u32(smem);

    const int tid  = threadIdx.x;
    const int wid  = tid >> 5;
    const int lane = tid & 31;
    const int l4   = lane >> 2;
    const int lq   = lane & 3;
    const int g8   = lane >> 3;
    const int r8   = lane & 7;
    const int warp_m  = (wid & 1) * 16;
    const int warp_n  = (wid >> 1) * 24;
    const int warp_n2 = (wid >> 1) * 32;
    const int m0 = blockIdx.x * TQ;
    const int t0 = m0 & (T_SEQ - 1);
    const int bb = m0 - t0;

    const uint32_t a_offQ = (uint32_t)((warp_m + (g8 & 1) * 8 + r8) * ROW2 + (g8 >> 1) * 16);
    const uint32_t a_offP = (uint32_t)((warp_m + (g8 & 1) * 8 + r8) * P_ROW + (g8 >> 1) * 16);
    const uint32_t b_lane = (uint32_t)((lane & 7) * ROW2 + ((lane >> 3) & 1) * 16);

    float acc[3][4];
#pragma unroll
    for (int i = 0; i < 3; i++)
#pragma unroll
        for (int e = 0; e < 4; e++) acc[i][e] = 0.0f;

    // ================= phase 1: scores =================
    for (int c = 0; c < 4; c++) {
#pragma unroll
        for (int j = 0; j < 2; j++) {
            const int g = tid + 256 * j;
            const int row = g >> 4, col = g & 15;
            const __half* gp = qkv + (size_t)(m0 + row) * QKV_N + c * 128 + col * 8;
            asm volatile("cp.async.cg.shared.global [%0], [%1], 16;"
                         :: "r"(sb + SM_Q + row * ROW2 + col * 16), "l"(gp) : "memory");
        }
#pragma unroll
        for (int j = 0; j < 6; j++) {
            const int g = tid + 256 * j;
            const int row = g >> 4, col = g & 15;
            int jt = t0 + row - JOFF;
            jt = jt < 0 ? 0 : (jt > T_SEQ - 1 ? T_SEQ - 1 : jt);
            const __half* gp = qkv + (size_t)(bb + jt) * QKV_N + DM + c * 128 + col * 8;
            asm volatile("cp.async.cg.shared.global [%0], [%1], 16;"
                         :: "r"(sb + SM_K + row * ROW2 + col * 16), "l"(gp) : "memory");
        }
        asm volatile("cp.async.commit_group;" ::: "memory");
        asm volatile("cp.async.wait_group 0;" ::: "memory");
        __syncthreads();

#pragma unroll
        for (int kk = 0; kk < 8; kk++) {
            uint32_t a[4];
            ldm_x4(a, sb + SM_Q + a_offQ + kk * 32);
#pragma unroll
            for (int nt = 0; nt < 3; nt++) {
                uint32_t b[2];
                ldm_x2(b, sb + SM_K + (warp_n + nt * 8) * ROW2 + b_lane + kk * 32);
                mma_fp16(acc[nt], a, b);
            }
        }
        __syncthreads();
    }

    // ================= mask + softmax =================
    const float invs = 0.04419417382415922f;
#pragma unroll
    for (int nt = 0; nt < 3; nt++)
#pragma unroll
        for (int e = 0; e < 4; e++) {
            const int i = warp_m + l4 + (e >> 1) * 8;
            const int j = warp_n + nt * 8 + 2 * lq + (e & 1);
            const int dj = j - i;
            const int jt = t0 + j - JOFF;
            const bool ok = (dj >= 1) && (dj <= 63) && (jt >= 0) && (jt < T_SEQ);
            acc[nt][e] = ok ? acc[nt][e] * invs : -1e30f;
        }

    float mx0 = -1e30f, mx1 = -1e30f;
#pragma unroll
    for (int nt = 0; nt < 3; nt++) {
        mx0 = fmaxf(mx0, fmaxf(acc[nt][0], acc[nt][1]));
        mx1 = fmaxf(mx1, fmaxf(acc[nt][2], acc[nt][3]));
    }
    mx0 = fmaxf(mx0, __shfl_xor_sync(0xffffffffu, mx0, 1));
    mx0 = fmaxf(mx0, __shfl_xor_sync(0xffffffffu, mx0, 2));
    mx1 = fmaxf(mx1, __shfl_xor_sync(0xffffffffu, mx1, 1));
    mx1 = fmaxf(mx1, __shfl_xor_sync(0xffffffffu, mx1, 2));

    float* redm = (float*)(smem + SM_RM);
    float* reds = (float*)(smem + SM_RS);
    const int r0 = warp_m + l4, r1 = r0 + 8;
    if (lq == 0) {
        redm[r0 * 4 + (wid >> 1)] = mx0;
        redm[r1 * 4 + (wid >> 1)] = mx1;
    }
    __syncthreads();
    float gm0 = fmaxf(fmaxf(redm[r0 * 4 + 0], redm[r0 * 4 + 1]),
                      fmaxf(redm[r0 * 4 + 2], redm[r0 * 4 + 3]));
    float gm1 = fmaxf(fmaxf(redm[r1 * 4 + 0], redm[r1 * 4 + 1]),
                      fmaxf(redm[r1 * 4 + 2], redm[r1 * 4 + 3]));

    float s0 = 0.0f, s1 = 0.0f;
#pragma unroll
    for (int nt = 0; nt < 3; nt++) {
        acc[nt][0] = __expf(acc[nt][0] - gm0);
        acc[nt][1] = __expf(acc[nt][1] - gm0);
        acc[nt][2] = __expf(acc[nt][2] - gm1);
        acc[nt][3] = __expf(acc[nt][3] - gm1);
        s0 += acc[nt][0] + acc[nt][1];
        s1 += acc[nt][2] + acc[nt][3];
    }
    s0 += __shfl_xor_sync(0xffffffffu, s0, 1);
    s0 += __shfl_xor_sync(0xffffffffu, s0, 2);
    s1 += __shfl_xor_sync(0xffffffffu, s1, 1);
    s1 += __shfl_xor_sync(0xffffffffu, s1, 2);
    if (lq == 0) {
        reds[r0 * 4 + (wid >> 1)] = s0;
        reds[r1 * 4 + (wid >> 1)] = s1;
    }
    __syncthreads();
    const float inv0 = 1.0f / (reds[r0 * 4 + 0] + reds[r0 * 4 + 1] +
                               reds[r0 * 4 + 2] + reds[r0 * 4 + 3]);
    const float inv1 = 1.0f / (reds[r1 * 4 + 0] + reds[r1 * 4 + 1] +
                               reds[r1 * 4 + 2] + reds[r1 * 4 + 3]);

#pragma unroll
    for (int nt = 0; nt < 3; nt++) {
        const int jc = warp_n + nt * 8 + 2 * lq;
        __half2 p0 = __floats2half2_rn(acc[nt][0] * inv0, acc[nt][1] * inv0);
        __half2 p1 = __floats2half2_rn(acc[nt][2] * inv1, acc[nt][3] * inv1);
        *reinterpret_cast<uint32_t*>(smem + SM_Q + r0 * P_ROW + jc * 2) =
            *reinterpret_cast<uint32_t*>(&p0);
        *reinterpret_cast<uint32_t*>(smem + SM_Q + r1 * P_ROW + jc * 2) =
            *reinterpret_cast<uint32_t*>(&p1);
    }
    __syncthreads();

    // ================= phase 2: O = P @ V =================
    for (int c = 0; c < 4; c++) {
#pragma unroll
        for (int j = 0; j < 6; j++) {
            const int g = tid + 256 * j;
            const int row = g >> 4, col = g & 15;
            int jt = t0 + row - JOFF;
            jt = jt < 0 ? 0 : (jt > T_SEQ - 1 ? T_SEQ - 1 : jt);
            const __half* gp = qkv + (size_t)(bb + jt) * QKV_N + 2 * DM + c * 128 + col * 8;
            asm volatile("cp.async.cg.shared.global [%0], [%1], 16;"
                         :: "r"(sb + SM_K + row * ROW2 + col * 16), "l"(gp) : "memory");
        }
        asm volatile("cp.async.commit_group;" ::: "memory");
        asm volatile("cp.async.wait_group 0;" ::: "memory");
        __syncthreads();

        float oacc[4][4];
#pragma unroll
        for (int i = 0; i < 4; i++)
#pragma unroll
            for (int e = 0; e < 4; e++) oacc[i][e] = 0.0f;

#pragma unroll
        for (int kk = 0; kk < 6; kk++) {
            uint32_t a[4];
            ldm_x4(a, sb + SM_Q + a_offP + kk * 32);
#pragma unroll
            for (int nt = 0; nt < 4; nt++) {
                uint32_t b[2];
                ldm_x2_t(b, sb + SM_K + (kk * 16 + (lane & 15)) * ROW2
                              + (warp_n2 + nt * 8) * 2);
                mma_fp16(oacc[nt], a, b);
            }
        }

#pragma unroll
        for (int nt = 0; nt < 4; nt++) {
            const int col = c * 128 + warp_n2 + nt * 8 + 2 * lq;
            __half2 h0 = __floats2half2_rn(oacc[nt][0], oacc[nt][1]);
            __half2 h1 = __floats2half2_rn(oacc[nt][2], oacc[nt][3]);
            *reinterpret_cast<uint32_t*>(oh + (size_t)(m0 + r0) * DM + col) =
                *reinterpret_cast<uint32_t*>(&h0);
            *reinterpret_cast<uint32_t*>(oh + (size_t)(m0 + r1) * DM + col) =
                *reinterpret_cast<uint32_t*>(&h1);
        }
        __syncthreads();
    }
}

// ---------------------------------------------------------------------------
extern "C" void kernel_launch(void* const* d_in, const int* in_sizes, int n_in,
                              void* d_out, int out_size)
{
    const float* x      = (const float*)d_in[0];
    const float* w_qkv  = (const float*)d_in[1];
    const float* b_qkv  = (const float*)d_in[2];
    const float* w_proj = (const float*)d_in[3];
    const float* b_proj = (const float*)d_in[4];
    float* out = (float*)d_out;

    __half *qkvh, *xh, *wqh, *wph, *ah;
    cudaGetSymbolAddress((void**)&qkvh, g_qkvh);
    cudaGetSymbolAddress((void**)&xh,  g_xh);
    cudaGetSymbolAddress((void**)&wqh, g_wqh);
    cudaGetSymbolAddress((void**)&wph, g_wph);
    cudaGetSymbolAddress((void**)&ah,  g_ah);

    static bool attr_set = false;
    if (!attr_set) {
        cudaFuncSetAttribute((const void*)gemm_fp16<128, 1>,
                             cudaFuncAttributeMaxDynamicSharedMemorySize, GEMM_SMEM_128);
        cudaFuncSetAttribute((const void*)gemm_fp16<64, 0>,
                             cudaFuncAttributeMaxDynamicSharedMemorySize, GEMM_SMEM_64);
        attr_set = true;
    }

    // 0) fused fp16 converts (one launch)
    const int n0 = NROWS * DM / 4, n1 = QKV_N * DM / 4, n2 = DM * DM / 4;
    conv_fp16_3<<<(n0 + n1 + n2 + 255) / 256, 256>>>(
        (const float4*)x, xh, n0,
        (const float4*)w_qkv, wqh, n1,
        (const float4*)w_proj, wph, n2);

    // 1) qkv = x @ w_qkv^T + b_qkv   [4096,1536], fp16 out  (384 CTAs)
    gemm_fp16<128, 1><<<dim3(QKV_N / 128, NROWS / 128), 256, GEMM_SMEM_128>>>(
        QKV_N, DM / 64, xh, wqh, b_qkv, qkvh);

    // 2) tensor-core local attention
    attn_mma<<<NROWS / TQ, 256, ATTN_SMEM>>>(qkvh, ah);

    // 3) out = att @ w_proj^T + b_proj  (fp32 out, BM=64 -> 256 CTAs)
    gemm_fp16<64, 0><<<dim3(DM / 128, NROWS / 64), 256, GEMM_SMEM_64>>>(
        DM, DM / 64, ah, wph, b_proj, out);
}

// round 13
// speedup vs baseline: 1.0435x; 1.0435x over previous
#include <cuda_runtime.h>
#include <cuda_fp16.h>
#include <cstdint>

#define T_SEQ   2048
#define BATCH   2
#define DM      512
#define NROWS   (BATCH * T_SEQ)   // 4096
#define QKV_N   (3 * DM)          // 1536
#define WIN     32
#define WW      (2 * WIN - 1)     // 63

// ---------------- scratch (__device__ globals: allocation-free rule) -------
__device__ __half g_qkvh[NROWS * QKV_N];     // fp16 q|k|v
__device__ __half g_xh[NROWS * DM];          // fp16 x
__device__ __half g_wqh[QKV_N * DM];         // fp16 w_qkv
__device__ __half g_wph[DM * DM];            // fp16 w_proj
__device__ __half g_ah[NROWS * DM];          // fp16 attention output

// ---------------- helpers ---------------------------------------------------
__device__ __forceinline__ uint32_t smem_u32(const void* p) {
    uint32_t a;
    asm("{ .reg .u64 t; cvta.to.shared.u64 t, %1; cvt.u32.u64 %0, t; }"
        : "=r"(a) : "l"(p));
    return a;
}

__device__ __forceinline__ void mma_fp16(float* c, const uint32_t* a, const uint32_t* b) {
    asm volatile(
        "mma.sync.aligned.m16n8k16.row.col.f32.f16.f16.f32 "
        "{%0,%1,%2,%3}, {%4,%5,%6,%7}, {%8,%9}, {%0,%1,%2,%3};"
        : "+f"(c[0]), "+f"(c[1]), "+f"(c[2]), "+f"(c[3])
        : "r"(a[0]), "r"(a[1]), "r"(a[2]), "r"(a[3]), "r"(b[0]), "r"(b[1]));
}

__device__ __forceinline__ void ldm_x4(uint32_t* d, uint32_t addr) {
    asm volatile("ldmatrix.sync.aligned.m8n8.x4.shared.b16 {%0,%1,%2,%3}, [%4];"
                 : "=r"(d[0]), "=r"(d[1]), "=r"(d[2]), "=r"(d[3]) : "r"(addr));
}
__device__ __forceinline__ void ldm_x2(uint32_t* d, uint32_t addr) {
    asm volatile("ldmatrix.sync.aligned.m8n8.x2.shared.b16 {%0,%1}, [%2];"
                 : "=r"(d[0]), "=r"(d[1]) : "r"(addr));
}
__device__ __forceinline__ void ldm_x2_t(uint32_t* d, uint32_t addr) {
    asm volatile("ldmatrix.sync.aligned.m8n8.x2.trans.shared.b16 {%0,%1}, [%2];"
                 : "=r"(d[0]), "=r"(d[1]) : "r"(addr));
}

// ---------------- GEMM smem geometry: K-chunk 64, 3 stages ------------------
#define ROWB    144
#define TILEB   (128 * ROWB)                 // 18432 B : [128 x 64fp16]
#define STAGEB  (2 * TILEB)                  // A | B = 36864 B
#define NSTAGE  3
#define GEMM_SMEM (NSTAGE * STAGEB)          // 110592 B -> 2 CTAs/SM

// ---------------------------------------------------------------------------
// fused fp32 -> fp16 convert for 3 arrays (one launch)
// ---------------------------------------------------------------------------
__global__ __launch_bounds__(256) void conv_fp16_3(
    const float4* __restrict__ s0, __half* __restrict__ d0, int n0,
    const float4* __restrict__ s1, __half* __restrict__ d1, int n1,
    const float4* __restrict__ s2, __half* __restrict__ d2, int n2)
{
    int i = blockIdx.x * blockDim.x + threadIdx.x;
    const float4* s; __half* d; int off;
    if (i < n0)           { s = s0; d = d0; off = i; }
    else if (i < n0 + n1) { s = s1; d = d1; off = i - n0; }
    else if (i < n0 + n1 + n2) { s = s2; d = d2; off = i - n0 - n1; }
    else return;
    float4 v = s[off];
    __half2 lo = __floats2half2_rn(v.x, v.y);
    __half2 hi = __floats2half2_rn(v.z, v.w);
    uint2 r;
    r.x = *reinterpret_cast<uint32_t*>(&lo);
    r.y = *reinterpret_cast<uint32_t*>(&hi);
    reinterpret_cast<uint2*>(d)[off] = r;
}

// ---------------------------------------------------------------------------
// fp16 HMMA GEMM: C[M,Ntot] = A[M,K] @ B[Ntot,K]^T + bias (fp32 accum)
// CTA 128x128, 8 warps x (64x32), K-chunk 64, 3-stage cp.async pipeline with
// early issue: wait(c) -> sync -> issue(c+2) -> compute(c).
// ---------------------------------------------------------------------------
template<int HALF_OUT>
__global__ __launch_bounds__(256, 2) void gemm_fp16(
    int Ntot, int kchunks,
    const __half* __restrict__ A, const __half* __restrict__ B,
    const float* __restrict__ bias, void* __restrict__ Cv)
{
    extern __shared__ __align__(16) char smem[];
    const uint32_t sbase = smem_u32(smem);

    const int tid    = threadIdx.x;
    const int wid    = tid >> 5;
    const int lane   = tid & 31;
    const int l4     = lane >> 2;
    const int lq     = lane & 3;
    const int warp_m = (wid & 1) * 64;
    const int warp_n = (wid >> 1) * 32;
    const int m0     = blockIdx.y * 128;
    const int n0     = blockIdx.x * 128;
    const int K      = kchunks * 64;

    const int g8 = lane >> 3;
    const int r8 = lane & 7;
    const uint32_t a_off  = (uint32_t)((warp_m + (g8 & 1) * 8 + r8) * ROWB + (g8 >> 1) * 16);
    const uint32_t b_off4 = (uint32_t)((warp_n + (g8 >> 1) * 8 + r8) * ROWB + (g8 & 1) * 16);

    auto issue_stage = [&](int c, int buf) {
#pragma unroll
        for (int j = 0; j < 4; j++) {
            const int idx = tid + 256 * j;
            const int row = idx >> 3;
            const int c16 = idx & 7;
            const __half* gp = A + (size_t)(m0 + row) * K + c * 64 + c16 * 8;
            const uint32_t sa = sbase + buf * STAGEB + row * ROWB + c16 * 16;
            asm volatile("cp.async.cg.shared.global [%0], [%1], 16;"
                         :: "r"(sa), "l"(gp) : "memory");
        }
#pragma unroll
        for (int j = 0; j < 4; j++) {
            const int idx = tid + 256 * j;
            const int row = idx >> 3;
            const int c16 = idx & 7;
            const __half* gp = B + (size_t)(n0 + row) * K + c * 64 + c16 * 8;
            const uint32_t sa = sbase + buf * STAGEB + TILEB + row * ROWB + c16 * 16;
            asm volatile("cp.async.cg.shared.global [%0], [%1], 16;"
                         :: "r"(sa), "l"(gp) : "memory");
        }
        asm volatile("cp.async.commit_group;" ::: "memory");
    };

    float acc[4][4][4];
#pragma unroll
    for (int i = 0; i < 4; i++)
#pragma unroll
        for (int j = 0; j < 4; j++)
#pragma unroll
            for (int r = 0; r < 4; r++) acc[i][j][r] = 0.0f;

    issue_stage(0, 0);
    if (kchunks > 1) issue_stage(1, 1);

    int buf = 0;
    for (int c = 0; c < kchunks; c++) {
        // wait for chunk c (keep up to 2 younger groups in flight)
        if (c + 2 <= kchunks - 1)      asm volatile("cp.async.wait_group 2;" ::: "memory");
        else if (c + 1 <= kchunks - 1) asm volatile("cp.async.wait_group 1;" ::: "memory");
        else                           asm volatile("cp.async.wait_group 0;" ::: "memory");
        __syncthreads();

        // early issue: chunk c+2 into the buffer freed by chunk c-1
        if (c + 2 < kchunks) {
            int nb = buf + 2; if (nb >= NSTAGE) nb -= NSTAGE;
            issue_stage(c + 2, nb);
        }

        const uint32_t Ab = sbase + buf * STAGEB;
        const uint32_t Bb = Ab + TILEB;

#pragma unroll
        for (int kk = 0; kk < 4; kk++) {
            uint32_t a[4][4];
#pragma unroll
            for (int mt = 0; mt < 4; mt++)
                ldm_x4(a[mt], Ab + a_off + mt * 16 * ROWB + kk * 32);
#pragma unroll
            for (int np = 0; np < 2; np++) {
                uint32_t b4[4];
                ldm_x4(b4, Bb + b_off4 + np * 16 * ROWB + kk * 32);
#pragma unroll
                for (int mt = 0; mt < 4; mt++)
                    mma_fp16(acc[mt][np * 2 + 0], a[mt], b4 + 0);
#pragma unroll
                for (int mt = 0; mt < 4; mt++)
                    mma_fp16(acc[mt][np * 2 + 1], a[mt], b4 + 2);
            }
        }

        if (++buf == NSTAGE) buf = 0;
    }

    // ---- epilogue: bias add, fp32 or fp16 out ----
#pragma unroll
    for (int nt = 0; nt < 4; nt++) {
        const int col = n0 + warp_n + nt * 8 + 2 * lq;
        const float2 bv = *reinterpret_cast<const float2*>(bias + col);
#pragma unroll
        for (int mt = 0; mt < 4; mt++) {
            const int row = m0 + warp_m + mt * 16 + l4;
            float2 r0, r1;
            r0.x = acc[mt][nt][0] + bv.x;
            r0.y = acc[mt][nt][1] + bv.y;
            r1.x = acc[mt][nt][2] + bv.x;
            r1.y = acc[mt][nt][3] + bv.y;
            if (HALF_OUT) {
                __half* C = (__half*)Cv;
                __half2 h0 = __floats2half2_rn(r0.x, r0.y);
                __half2 h1 = __floats2half2_rn(r1.x, r1.y);
                *reinterpret_cast<uint32_t*>(C + (size_t)row * Ntot + col) =
                    *reinterpret_cast<uint32_t*>(&h0);
                *reinterpret_cast<uint32_t*>(C + (size_t)(row + 8) * Ntot + col) =
                    *reinterpret_cast<uint32_t*>(&h1);
            } else {
                float* C = (float*)Cv;
                *reinterpret_cast<float2*>(C + (size_t)row * Ntot + col) = r0;
                *reinterpret_cast<float2*>(C + (size_t)(row + 8) * Ntot + col) = r1;
            }
        }
    }
}

// ---------------------------------------------------------------------------
// Tensor-core local attention (unchanged, proven at ~11 us).
// ---------------------------------------------------------------------------
#define TQ     32
#define SPAN   96
#define JOFF   32
#define ROW2   272
#define P_ROW  208
#define SM_Q   0
#define SM_K   8704
#define SM_RM  34816
#define SM_RS  35328
#define ATTN_SMEM 35840

__global__ __launch_bounds__(256) void attn_mma(
    const __half* __restrict__ qkv, __half* __restrict__ oh)
{
    extern __shared__ __align__(16) char smem[];
    const uint32_t sb = smem_u32(smem);

    const int tid  = threadIdx.x;
    const int wid  = tid >> 5;
    const int lane = tid & 31;
    const int l4   = lane >> 2;
    const int lq   = lane & 3;
    const int g8   = lane >> 3;
    const int r8   = lane & 7;
    const int warp_m  = (wid & 1) * 16;
    const int warp_n  = (wid >> 1) * 24;
    const int warp_n2 = (wid >> 1) * 32;
    const int m0 = blockIdx.x * TQ;
    const int t0 = m0 & (T_SEQ - 1);
    const int bb = m0 - t0;

    const uint32_t a_offQ = (uint32_t)((warp_m + (g8 & 1) * 8 + r8) * ROW2 + (g8 >> 1) * 16);
    const uint32_t a_offP = (uint32_t)((warp_m + (g8 & 1) * 8 + r8) * P_ROW + (g8 >> 1) * 16);
    const uint32_t b_lane = (uint32_t)((lane & 7) * ROW2 + ((lane >> 3) & 1) * 16);

    float acc[3][4];
#pragma unroll
    for (int i = 0; i < 3; i++)
#pragma unroll
        for (int e = 0; e < 4; e++) acc[i][e] = 0.0f;

    // ================= phase 1: scores =================
    for (int c = 0; c < 4; c++) {
#pragma unroll
        for (int j = 0; j < 2; j++) {
            const int g = tid + 256 * j;
            const int row = g >> 4, col = g & 15;
            const __half* gp = qkv + (size_t)(m0 + row) * QKV_N + c * 128 + col * 8;
            asm volatile("cp.async.cg.shared.global [%0], [%1], 16;"
                         :: "r"(sb + SM_Q + row * ROW2 + col * 16), "l"(gp) : "memory");
        }
#pragma unroll
        for (int j = 0; j < 6; j++) {
            const int g = tid + 256 * j;
            const int row = g >> 4, col = g & 15;
            int jt = t0 + row - JOFF;
            jt = jt < 0 ? 0 : (jt > T_SEQ - 1 ? T_SEQ - 1 : jt);
            const __half* gp = qkv + (size_t)(bb + jt) * QKV_N + DM + c * 128 + col * 8;
            asm volatile("cp.async.cg.shared.global [%0], [%1], 16;"
                         :: "r"(sb + SM_K + row * ROW2 + col * 16), "l"(gp) : "memory");
        }
        asm volatile("cp.async.commit_group;" ::: "memory");
        asm volatile("cp.async.wait_group 0;" ::: "memory");
        __syncthreads();

#pragma unroll
        for (int kk = 0; kk < 8; kk++) {
            uint32_t a[4];
            ldm_x4(a, sb + SM_Q + a_offQ + kk * 32);
#pragma unroll
            for (int nt = 0; nt < 3; nt++) {
                uint32_t b[2];
                ldm_x2(b, sb + SM_K + (warp_n + nt * 8) * ROW2 + b_lane + kk * 32);
                mma_fp16(acc[nt], a, b);
            }
        }
        __syncthreads();
    }

    // ================= mask + softmax =================
    const float invs = 0.04419417382415922f;
#pragma unroll
    for (int nt = 0; nt < 3; nt++)
#pragma unroll
        for (int e = 0; e < 4; e++) {
            const int i = warp_m + l4 + (e >> 1) * 8;
            const int j = warp_n + nt * 8 + 2 * lq + (e & 1);
            const int dj = j - i;
            const int jt = t0 + j - JOFF;
            const bool ok = (dj >= 1) && (dj <= 63) && (jt >= 0) && (jt < T_SEQ);
            acc[nt][e] = ok ? acc[nt][e] * invs : -1e30f;
        }

    float mx0 = -1e30f, mx1 = -1e30f;
#pragma unroll
    for (int nt = 0; nt < 3; nt++) {
        mx0 = fmaxf(mx0, fmaxf(acc[nt][0], acc[nt][1]));
        mx1 = fmaxf(mx1, fmaxf(acc[nt][2], acc[nt][3]));
    }
    mx0 = fmaxf(mx0, __shfl_xor_sync(0xffffffffu, mx0, 1));
    mx0 = fmaxf(mx0, __shfl_xor_sync(0xffffffffu, mx0, 2));
    mx1 = fmaxf(mx1, __shfl_xor_sync(0xffffffffu, mx1, 1));
    mx1 = fmaxf(mx1, __shfl_xor_sync(0xffffffffu, mx1, 2));

    float* redm = (float*)(smem + SM_RM);
    float* reds = (float*)(smem + SM_RS);
    const int r0 = warp_m + l4, r1 = r0 + 8;
    if (lq == 0) {
        redm[r0 * 4 + (wid >> 1)] = mx0;
        redm[r1 * 4 + (wid >> 1)] = mx1;
    }
    __syncthreads();
    float gm0 = fmaxf(fmaxf(redm[r0 * 4 + 0], redm[r0 * 4 + 1]),
                      fmaxf(redm[r0 * 4 + 2], redm[r0 * 4 + 3]));
    float gm1 = fmaxf(fmaxf(redm[r1 * 4 + 0], redm[r1 * 4 + 1]),
                      fmaxf(redm[r1 * 4 + 2], redm[r1 * 4 + 3]));

    float s0 = 0.0f, s1 = 0.0f;
#pragma unroll
    for (int nt = 0; nt < 3; nt++) {
        acc[nt][0] = __expf(acc[nt][0] - gm0);
        acc[nt][1] = __expf(acc[nt][1] - gm0);
        acc[nt][2] = __expf(acc[nt][2] - gm1);
        acc[nt][3] = __expf(acc[nt][3] - gm1);
        s0 += acc[nt][0] + acc[nt][1];
        s1 += acc[nt][2] + acc[nt][3];
    }
    s0 += __shfl_xor_sync(0xffffffffu, s0, 1);
    s0 += __shfl_xor_sync(0xffffffffu, s0, 2);
    s1 += __shfl_xor_sync(0xffffffffu, s1, 1);
    s1 += __shfl_xor_sync(0xffffffffu, s1, 2);
    if (lq == 0) {
        reds[r0 * 4 + (wid >> 1)] = s0;
        reds[r1 * 4 + (wid >> 1)] = s1;
    }
    __syncthreads();
    const float inv0 = 1.0f / (reds[r0 * 4 + 0] + reds[r0 * 4 + 1] +
                               reds[r0 * 4 + 2] + reds[r0 * 4 + 3]);
    const float inv1 = 1.0f / (reds[r1 * 4 + 0] + reds[r1 * 4 + 1] +
                               reds[r1 * 4 + 2] + reds[r1 * 4 + 3]);

#pragma unroll
    for (int nt = 0; nt < 3; nt++) {
        const int jc = warp_n + nt * 8 + 2 * lq;
        __half2 p0 = __floats2half2_rn(acc[nt][0] * inv0, acc[nt][1] * inv0);
        __half2 p1 = __floats2half2_rn(acc[nt][2] * inv1, acc[nt][3] * inv1);
        *reinterpret_cast<uint32_t*>(smem + SM_Q + r0 * P_ROW + jc * 2) =
            *reinterpret_cast<uint32_t*>(&p0);
        *reinterpret_cast<uint32_t*>(smem + SM_Q + r1 * P_ROW + jc * 2) =
            *reinterpret_cast<uint32_t*>(&p1);
    }
    __syncthreads();

    // ================= phase 2: O = P @ V =================
    for (int c = 0; c < 4; c++) {
#pragma unroll
        for (int j = 0; j < 6; j++) {
            const int g = tid + 256 * j;
            const int row = g >> 4, col = g & 15;
            int jt = t0 + row - JOFF;
            jt = jt < 0 ? 0 : (jt > T_SEQ - 1 ? T_SEQ - 1 : jt);
            const __half* gp = qkv + (size_t)(bb + jt) * QKV_N + 2 * DM + c * 128 + col * 8;
            asm volatile("cp.async.cg.shared.global [%0], [%1], 16;"
                         :: "r"(sb + SM_K + row * ROW2 + col * 16), "l"(gp) : "memory");
        }
        asm volatile("cp.async.commit_group;" ::: "memory");
        asm volatile("cp.async.wait_group 0;" ::: "memory");
        __syncthreads();

        float oacc[4][4];
#pragma unroll
        for (int i = 0; i < 4; i++)
#pragma unroll
            for (int e = 0; e < 4; e++) oacc[i][e] = 0.0f;

#pragma unroll
        for (int kk = 0; kk < 6; kk++) {
            uint32_t a[4];
            ldm_x4(a, sb + SM_Q + a_offP + kk * 32);
#pragma unroll
            for (int nt = 0; nt < 4; nt++) {
                uint32_t b[2];
                ldm_x2_t(b, sb + SM_K + (kk * 16 + (lane & 15)) * ROW2
                              + (warp_n2 + nt * 8) * 2);
                mma_fp16(oacc[nt], a, b);
            }
        }

#pragma unroll
        for (int nt = 0; nt < 4; nt++) {
            const int col = c * 128 + warp_n2 + nt * 8 + 2 * lq;
            __half2 h0 = __floats2half2_rn(oacc[nt][0], oacc[nt][1]);
            __half2 h1 = __floats2half2_rn(oacc[nt][2], oacc[nt][3]);
            *reinterpret_cast<uint32_t*>(oh + (size_t)(m0 + r0) * DM + col) =
                *reinterpret_cast<uint32_t*>(&h0);
            *reinterpret_cast<uint32_t*>(oh + (size_t)(m0 + r1) * DM + col) =
                *reinterpret_cast<uint32_t*>(&h1);
        }
        __syncthreads();
    }
}

// ---------------------------------------------------------------------------
extern "C" void kernel_launch(void* const* d_in, const int* in_sizes, int n_in,
                              void* d_out, int out_size)
{
    const float* x      = (const float*)d_in[0];
    const float* w_qkv  = (const float*)d_in[1];
    const float* b_qkv  = (const float*)d_in[2];
    const float* w_proj = (const float*)d_in[3];
    const float* b_proj = (const float*)d_in[4];
    float* out = (float*)d_out;

    __half *qkvh, *xh, *wqh, *wph, *ah;
    cudaGetSymbolAddress((void**)&qkvh, g_qkvh);
    cudaGetSymbolAddress((void**)&xh,  g_xh);
    cudaGetSymbolAddress((void**)&wqh, g_wqh);
    cudaGetSymbolAddress((void**)&wph, g_wph);
    cudaGetSymbolAddress((void**)&ah,  g_ah);

    static bool attr_set = false;
    if (!attr_set) {
        cudaFuncSetAttribute((const void*)gemm_fp16<1>,
                             cudaFuncAttributeMaxDynamicSharedMemorySize, GEMM_SMEM);
        cudaFuncSetAttribute((const void*)gemm_fp16<0>,
                             cudaFuncAttributeMaxDynamicSharedMemorySize, GEMM_SMEM);
        attr_set = true;
    }

    // 0) fused fp16 converts (one launch)
    const int n0 = NROWS * DM / 4, n1 = QKV_N * DM / 4, n2 = DM * DM / 4;
    conv_fp16_3<<<(n0 + n1 + n2 + 255) / 256, 256>>>(
        (const float4*)x, xh, n0,
        (const float4*)w_qkv, wqh, n1,
        (const float4*)w_proj, wph, n2);

    // 1) qkv = x @ w_qkv^T + b_qkv   [4096,1536], fp16 out  (384 CTAs)
    gemm_fp16<1><<<dim3(QKV_N / 128, NROWS / 128), 256, GEMM_SMEM>>>(
        QKV_N, DM / 64, xh, wqh, b_qkv, qkvh);

    // 2) tensor-core local attention
    attn_mma<<<NROWS / TQ, 256, ATTN_SMEM>>>(qkvh, ah);

    // 3) out = att @ w_proj^T + b_proj  (fp32 out, 128 CTAs)
    gemm_fp16<0><<<dim3(DM / 128, NROWS / 128), 256, GEMM_SMEM>>>(
        DM, DM / 64, ah, wph, b_proj, out);
}

// round 14
// speedup vs baseline: 1.0735x; 1.0288x over previous
#include <cuda_runtime.h>
#include <cuda_fp16.h>
#include <cstdint>

#define T_SEQ   2048
#define BATCH   2
#define DM      512
#define NROWS   (BATCH * T_SEQ)   // 4096
#define QKV_N   (3 * DM)          // 1536
#define WIN     32
#define WW      (2 * WIN - 1)     // 63

// ---------------- scratch (__device__ globals: allocation-free rule) -------
__device__ __half g_qkvh[NROWS * QKV_N];     // fp16 q|k|v
__device__ __half g_xh[NROWS * DM];          // fp16 x
__device__ __half g_wqh[QKV_N * DM];         // fp16 w_qkv
__device__ __half g_wph[DM * DM];            // fp16 w_proj
__device__ __half g_ah[NROWS * DM];          // fp16 attention output

// ---------------- helpers ---------------------------------------------------
__device__ __forceinline__ uint32_t smem_u32(const void* p) {
    uint32_t a;
    asm("{ .reg .u64 t; cvta.to.shared.u64 t, %1; cvt.u32.u64 %0, t; }"
        : "=r"(a) : "l"(p));
    return a;
}

__device__ __forceinline__ void mma_fp16(float* c, const uint32_t* a, const uint32_t* b) {
    asm volatile(
        "mma.sync.aligned.m16n8k16.row.col.f32.f16.f16.f32 "
        "{%0,%1,%2,%3}, {%4,%5,%6,%7}, {%8,%9}, {%0,%1,%2,%3};"
        : "+f"(c[0]), "+f"(c[1]), "+f"(c[2]), "+f"(c[3])
        : "r"(a[0]), "r"(a[1]), "r"(a[2]), "r"(a[3]), "r"(b[0]), "r"(b[1]));
}

__device__ __forceinline__ void ldm_x4(uint32_t* d, uint32_t addr) {
    asm volatile("ldmatrix.sync.aligned.m8n8.x4.shared.b16 {%0,%1,%2,%3}, [%4];"
                 : "=r"(d[0]), "=r"(d[1]), "=r"(d[2]), "=r"(d[3]) : "r"(addr));
}
__device__ __forceinline__ void ldm_x2(uint32_t* d, uint32_t addr) {
    asm volatile("ldmatrix.sync.aligned.m8n8.x2.shared.b16 {%0,%1}, [%2];"
                 : "=r"(d[0]), "=r"(d[1]) : "r"(addr));
}
__device__ __forceinline__ void ldm_x2_t(uint32_t* d, uint32_t addr) {
    asm volatile("ldmatrix.sync.aligned.m8n8.x2.trans.shared.b16 {%0,%1}, [%2];"
                 : "=r"(d[0]), "=r"(d[1]) : "r"(addr));
}

// ---------------- GEMM smem geometry: K-chunk 64, 3 stages ------------------
#define ROWB    144
#define TILEB   (128 * ROWB)                 // 18432 B : [128 x 64fp16]
#define STAGEB  (2 * TILEB)                  // A | B = 36864 B
#define NSTAGE  3
#define GEMM_SMEM (NSTAGE * STAGEB)          // 110592 B

// ---------------------------------------------------------------------------
// fused fp32 -> fp16 convert for 3 arrays (one launch)
// ---------------------------------------------------------------------------
__global__ __launch_bounds__(256) void conv_fp16_3(
    const float4* __restrict__ s0, __half* __restrict__ d0, int n0,
    const float4* __restrict__ s1, __half* __restrict__ d1, int n1,
    const float4* __restrict__ s2, __half* __restrict__ d2, int n2)
{
    int i = blockIdx.x * blockDim.x + threadIdx.x;
    const float4* s; __half* d; int off;
    if (i < n0)           { s = s0; d = d0; off = i; }
    else if (i < n0 + n1) { s = s1; d = d1; off = i - n0; }
    else if (i < n0 + n1 + n2) { s = s2; d = d2; off = i - n0 - n1; }
    else return;
    float4 v = s[off];
    __half2 lo = __floats2half2_rn(v.x, v.y);
    __half2 hi = __floats2half2_rn(v.z, v.w);
    uint2 r;
    r.x = *reinterpret_cast<uint32_t*>(&lo);
    r.y = *reinterpret_cast<uint32_t*>(&hi);
    reinterpret_cast<uint2*>(d)[off] = r;
}

// ---------------------------------------------------------------------------
// fp16 HMMA GEMM: C[M,Ntot] = A[M,K] @ B[Ntot,K]^T + bias (fp32 accum)
// CTA 128x128, K-chunk 64, 3-stage cp.async pipeline with early issue.
// NWARP=8 : warps of 64x32 (proven fast, high work per SM)
// NWARP=16: warps of 32x32 (for low-CTA-count grids: 4 warps/SMSP latency hide)
// ---------------------------------------------------------------------------
template<int NWARP, int HALF_OUT>
__global__ __launch_bounds__(NWARP * 32, (NWARP == 8) ? 2 : 1) void gemm_fp16(
    int Ntot, int kchunks,
    const __half* __restrict__ A, const __half* __restrict__ B,
    const float* __restrict__ bias, void* __restrict__ Cv)
{
    constexpr int TH = NWARP * 32;
    constexpr int MT = (NWARP == 8) ? 4 : 2;     // 16-row subtiles per warp

    extern __shared__ __align__(16) char smem[];
    const uint32_t sbase = smem_u32(smem);

    const int tid    = threadIdx.x;
    const int wid    = tid >> 5;
    const int lane   = tid & 31;
    const int l4     = lane >> 2;
    const int lq     = lane & 3;
    const int warp_m = (NWARP == 8) ? (wid & 1) * 64 : (wid & 3) * 32;
    const int warp_n = (NWARP == 8) ? (wid >> 1) * 32 : (wid >> 2) * 32;
    const int m0     = blockIdx.y * 128;
    const int n0     = blockIdx.x * 128;
    const int K      = kchunks * 64;

    const int g8 = lane >> 3;
    const int r8 = lane & 7;
    const uint32_t a_off  = (uint32_t)((warp_m + (g8 & 1) * 8 + r8) * ROWB + (g8 >> 1) * 16);
    const uint32_t b_off4 = (uint32_t)((warp_n + (g8 >> 1) * 8 + r8) * ROWB + (g8 & 1) * 16);

    auto issue_stage = [&](int c, int buf) {
#pragma unroll
        for (int j = 0; j < 1024 / TH; j++) {
            const int idx = tid + TH * j;
            const int row = idx >> 3;
            const int c16 = idx & 7;
            const __half* gp = A + (size_t)(m0 + row) * K + c * 64 + c16 * 8;
            const uint32_t sa = sbase + buf * STAGEB + row * ROWB + c16 * 16;
            asm volatile("cp.async.cg.shared.global [%0], [%1], 16;"
                         :: "r"(sa), "l"(gp) : "memory");
        }
#pragma unroll
        for (int j = 0; j < 1024 / TH; j++) {
            const int idx = tid + TH * j;
            const int row = idx >> 3;
            const int c16 = idx & 7;
            const __half* gp = B + (size_t)(n0 + row) * K + c * 64 + c16 * 8;
            const uint32_t sa = sbase + buf * STAGEB + TILEB + row * ROWB + c16 * 16;
            asm volatile("cp.async.cg.shared.global [%0], [%1], 16;"
                         :: "r"(sa), "l"(gp) : "memory");
        }
        asm volatile("cp.async.commit_group;" ::: "memory");
    };

    float acc[MT][4][4];
#pragma unroll
    for (int i = 0; i < MT; i++)
#pragma unroll
        for (int j = 0; j < 4; j++)
#pragma unroll
            for (int r = 0; r < 4; r++) acc[i][j][r] = 0.0f;

    issue_stage(0, 0);
    if (kchunks > 1) issue_stage(1, 1);

    int buf = 0;
    for (int c = 0; c < kchunks; c++) {
        if (c + 2 <= kchunks - 1)      asm volatile("cp.async.wait_group 2;" ::: "memory");
        else if (c + 1 <= kchunks - 1) asm volatile("cp.async.wait_group 1;" ::: "memory");
        else                           asm volatile("cp.async.wait_group 0;" ::: "memory");
        __syncthreads();

        if (c + 2 < kchunks) {
            int nb = buf + 2; if (nb >= NSTAGE) nb -= NSTAGE;
            issue_stage(c + 2, nb);
        }

        const uint32_t Ab = sbase + buf * STAGEB;
        const uint32_t Bb = Ab + TILEB;

#pragma unroll
        for (int kk = 0; kk < 4; kk++) {
            uint32_t a[MT][4];
#pragma unroll
            for (int mt = 0; mt < MT; mt++)
                ldm_x4(a[mt], Ab + a_off + mt * 16 * ROWB + kk * 32);
#pragma unroll
            for (int np = 0; np < 2; np++) {
                uint32_t b4[4];
                ldm_x4(b4, Bb + b_off4 + np * 16 * ROWB + kk * 32);
#pragma unroll
                for (int mt = 0; mt < MT; mt++)
                    mma_fp16(acc[mt][np * 2 + 0], a[mt], b4 + 0);
#pragma unroll
                for (int mt = 0; mt < MT; mt++)
                    mma_fp16(acc[mt][np * 2 + 1], a[mt], b4 + 2);
            }
        }

        if (++buf == NSTAGE) buf = 0;
    }

    // ---- epilogue: bias add, fp32 or fp16 out ----
#pragma unroll
    for (int nt = 0; nt < 4; nt++) {
        const int col = n0 + warp_n + nt * 8 + 2 * lq;
        const float2 bv = *reinterpret_cast<const float2*>(bias + col);
#pragma unroll
        for (int mt = 0; mt < MT; mt++) {
            const int row = m0 + warp_m + mt * 16 + l4;
            float2 r0, r1;
            r0.x = acc[mt][nt][0] + bv.x;
            r0.y = acc[mt][nt][1] + bv.y;
            r1.x = acc[mt][nt][2] + bv.x;
            r1.y = acc[mt][nt][3] + bv.y;
            if (HALF_OUT) {
                __half* C = (__half*)Cv;
                __half2 h0 = __floats2half2_rn(r0.x, r0.y);
                __half2 h1 = __floats2half2_rn(r1.x, r1.y);
                *reinterpret_cast<uint32_t*>(C + (size_t)row * Ntot + col) =
                    *reinterpret_cast<uint32_t*>(&h0);
                *reinterpret_cast<uint32_t*>(C + (size_t)(row + 8) * Ntot + col) =
                    *reinterpret_cast<uint32_t*>(&h1);
            } else {
                float* C = (float*)Cv;
                *reinterpret_cast<float2*>(C + (size_t)row * Ntot + col) = r0;
                *reinterpret_cast<float2*>(C + (size_t)(row + 8) * Ntot + col) = r1;
            }
        }
    }
}

// ---------------------------------------------------------------------------
// Tensor-core local attention, pipelined: 8-chunk async stream QK0..3,V0..3
// through 2 stage buffers with 1-chunk lookahead; V0/V1 load during softmax.
// ---------------------------------------------------------------------------
#define TQ     32
#define JOFF   32
#define ROW2   272                       // 128 fp16 + 16B pad
#define P_ROW  208                       // 96 fp16 + 16B pad
#define ST_Q   0                         // Q: 32 x 272 = 8704
#define ST_K   8704                      // K/V: 96 x 272 = 26112
#define STAGE_A 34816                    // stage size
#define SM_P   (2 * STAGE_A)             // 69632, P: 32 x 208 = 6656
#define SM_RM  76288
#define SM_RS  76800
#define ATTN_SMEM 77312

__global__ __launch_bounds__(256) void attn_mma(
    const __half* __restrict__ qkv, __half* __restrict__ oh)
{
    extern __shared__ __align__(16) char smem[];
    const uint32_t sb = smem_u32(smem);

    const int tid  = threadIdx.x;
    const int wid  = tid >> 5;
    const int lane = tid & 31;
    const int l4   = lane >> 2;
    const int lq   = lane & 3;
    const int g8   = lane >> 3;
    const int r8   = lane & 7;
    const int warp_m  = (wid & 1) * 16;
    const int warp_n  = (wid >> 1) * 24;
    const int warp_n2 = (wid >> 1) * 32;
    const int m0 = blockIdx.x * TQ;
    const int t0 = m0 & (T_SEQ - 1);
    const int bb = m0 - t0;

    const uint32_t a_offQ = (uint32_t)((warp_m + (g8 & 1) * 8 + r8) * ROW2 + (g8 >> 1) * 16);
    const uint32_t a_offP = (uint32_t)((warp_m + (g8 & 1) * 8 + r8) * P_ROW + (g8 >> 1) * 16);
    const uint32_t b_lane = (uint32_t)((lane & 7) * ROW2 + ((lane >> 3) & 1) * 16);

    const uint32_t stg[2] = { sb, sb + STAGE_A };

    // chunk loaders (one commit group each)
    auto issue_qk = [&](int c, uint32_t s) {
#pragma unroll
        for (int j = 0; j < 2; j++) {
            const int g = tid + 256 * j;
            const int row = g >> 4, col = g & 15;
            const __half* gp = qkv + (size_t)(m0 + row) * QKV_N + c * 128 + col * 8;
            asm volatile("cp.async.cg.shared.global [%0], [%1], 16;"
                         :: "r"(s + ST_Q + row * ROW2 + col * 16), "l"(gp) : "memory");
        }
#pragma unroll
        for (int j = 0; j < 6; j++) {
            const int g = tid + 256 * j;
            const int row = g >> 4, col = g & 15;
            int jt = t0 + row - JOFF;
            jt = jt < 0 ? 0 : (jt > T_SEQ - 1 ? T_SEQ - 1 : jt);
            const __half* gp = qkv + (size_t)(bb + jt) * QKV_N + DM + c * 128 + col * 8;
            asm volatile("cp.async.cg.shared.global [%0], [%1], 16;"
                         :: "r"(s + ST_K + row * ROW2 + col * 16), "l"(gp) : "memory");
        }
        asm volatile("cp.async.commit_group;" ::: "memory");
    };
    auto issue_v = [&](int c, uint32_t s) {
#pragma unroll
        for (int j = 0; j < 6; j++) {
            const int g = tid + 256 * j;
            const int row = g >> 4, col = g & 15;
            int jt = t0 + row - JOFF;
            jt = jt < 0 ? 0 : (jt > T_SEQ - 1 ? T_SEQ - 1 : jt);
            const __half* gp = qkv + (size_t)(bb + jt) * QKV_N + 2 * DM + c * 128 + col * 8;
            asm volatile("cp.async.cg.shared.global [%0], [%1], 16;"
                         :: "r"(s + ST_K + row * ROW2 + col * 16), "l"(gp) : "memory");
        }
        asm volatile("cp.async.commit_group;" ::: "memory");
    };

    float acc[3][4];
#pragma unroll
    for (int i = 0; i < 3; i++)
#pragma unroll
        for (int e = 0; e < 4; e++) acc[i][e] = 0.0f;

    // prologue: QK0, QK1 in flight
    issue_qk(0, stg[0]);
    issue_qk(1, stg[1]);

    // ================= phase 1: scores (1-chunk lookahead) =================
    for (int c = 0; c < 4; c++) {
        asm volatile("cp.async.wait_group 1;" ::: "memory");
        __syncthreads();

        const uint32_t s = stg[c & 1];
#pragma unroll
        for (int kk = 0; kk < 8; kk++) {
            uint32_t a[4];
            ldm_x4(a, s + ST_Q + a_offQ + kk * 32);
#pragma unroll
            for (int nt = 0; nt < 3; nt++) {
                uint32_t b[2];
                ldm_x2(b, s + ST_K + (warp_n + nt * 8) * ROW2 + b_lane + kk * 32);
                mma_fp16(acc[nt], a, b);
            }
        }
        __syncthreads();

        // stream: c=0->QK2, c=1->QK3, c=2->V0, c=3->V1 (into the freed buffer)
        if (c < 2)      issue_qk(c + 2, stg[c & 1]);
        else            issue_v(c - 2, stg[c & 1]);
    }

    // ================= mask + softmax (V0/V1 in flight) =================
    const float invs = 0.04419417382415922f;   // 1/sqrt(512)
#pragma unroll
    for (int nt = 0; nt < 3; nt++)
#pragma unroll
        for (int e = 0; e < 4; e++) {
            const int i = warp_m + l4 + (e >> 1) * 8;
            const int j = warp_n + nt * 8 + 2 * lq + (e & 1);
            const int dj = j - i;
            const int jt = t0 + j - JOFF;
            const bool ok = (dj >= 1) && (dj <= 63) && (jt >= 0) && (jt < T_SEQ);
            acc[nt][e] = ok ? acc[nt][e] * invs : -1e30f;
        }

    float mx0 = -1e30f, mx1 = -1e30f;
#pragma unroll
    for (int nt = 0; nt < 3; nt++) {
        mx0 = fmaxf(mx0, fmaxf(acc[nt][0], acc[nt][1]));
        mx1 = fmaxf(mx1, fmaxf(acc[nt][2], acc[nt][3]));
    }
    mx0 = fmaxf(mx0, __shfl_xor_sync(0xffffffffu, mx0, 1));
    mx0 = fmaxf(mx0, __shfl_xor_sync(0xffffffffu, mx0, 2));
    mx1 = fmaxf(mx1, __shfl_xor_sync(0xffffffffu, mx1, 1));
    mx1 = fmaxf(mx1, __shfl_xor_sync(0xffffffffu, mx1, 2));

    float* redm = (float*)(smem + SM_RM);
    float* reds = (float*)(smem + SM_RS);
    const int r0 = warp_m + l4, r1 = r0 + 8;
    if (lq == 0) {
        redm[r0 * 4 + (wid >> 1)] = mx0;
        redm[r1 * 4 + (wid >> 1)] = mx1;
    }
    __syncthreads();
    float gm0 = fmaxf(fmaxf(redm[r0 * 4 + 0], redm[r0 * 4 + 1]),
                      fmaxf(redm[r0 * 4 + 2], redm[r0 * 4 + 3]));
    float gm1 = fmaxf(fmaxf(redm[r1 * 4 + 0], redm[r1 * 4 + 1]),
                      fmaxf(redm[r1 * 4 + 2], redm[r1 * 4 + 3]));

    float s0 = 0.0f, s1 = 0.0f;
#pragma unroll
    for (int nt = 0; nt < 3; nt++) {
        acc[nt][0] = __expf(acc[nt][0] - gm0);
        acc[nt][1] = __expf(acc[nt][1] - gm0);
        acc[nt][2] = __expf(acc[nt][2] - gm1);
        acc[nt][3] = __expf(acc[nt][3] - gm1);
        s0 += acc[nt][0] + acc[nt][1];
        s1 += acc[nt][2] + acc[nt][3];
    }
    s0 += __shfl_xor_sync(0xffffffffu, s0, 1);
    s0 += __shfl_xor_sync(0xffffffffu, s0, 2);
    s1 += __shfl_xor_sync(0xffffffffu, s1, 1);
    s1 += __shfl_xor_sync(0xffffffffu, s1, 2);
    if (lq == 0) {
        reds[r0 * 4 + (wid >> 1)] = s0;
        reds[r1 * 4 + (wid >> 1)] = s1;
    }
    __syncthreads();
    const float inv0 = 1.0f / (reds[r0 * 4 + 0] + reds[r0 * 4 + 1] +
                               reds[r0 * 4 + 2] + reds[r0 * 4 + 3]);
    const float inv1 = 1.0f / (reds[r1 * 4 + 0] + reds[r1 * 4 + 1] +
                               reds[r1 * 4 + 2] + reds[r1 * 4 + 3]);

#pragma unroll
    for (int nt = 0; nt < 3; nt++) {
        const int jc = warp_n + nt * 8 + 2 * lq;
        __half2 p0 = __floats2half2_rn(acc[nt][0] * inv0, acc[nt][1] * inv0);
        __half2 p1 = __floats2half2_rn(acc[nt][2] * inv1, acc[nt][3] * inv1);
        *reinterpret_cast<uint32_t*>(smem + SM_P + r0 * P_ROW + jc * 2) =
            *reinterpret_cast<uint32_t*>(&p0);
        *reinterpret_cast<uint32_t*>(smem + SM_P + r1 * P_ROW + jc * 2) =
            *reinterpret_cast<uint32_t*>(&p1);
    }
    __syncthreads();

    // ================= phase 2: O = P @ V (1-chunk lookahead) ==============
    for (int c = 0; c < 4; c++) {
        if (c == 3) asm volatile("cp.async.wait_group 0;" ::: "memory");
        else        asm volatile("cp.async.wait_group 1;" ::: "memory");
        __syncthreads();

        const uint32_t s = stg[c & 1];
        float oacc[4][4];
#pragma unroll
        for (int i = 0; i < 4; i++)
#pragma unroll
            for (int e = 0; e < 4; e++) oacc[i][e] = 0.0f;

#pragma unroll
        for (int kk = 0; kk < 6; kk++) {
            uint32_t a[4];
            ldm_x4(a, sb + SM_P + a_offP + kk * 32);
#pragma unroll
            for (int nt = 0; nt < 4; nt++) {
                uint32_t b[2];
                ldm_x2_t(b, s + ST_K + (kk * 16 + (lane & 15)) * ROW2
                              + (warp_n2 + nt * 8) * 2);
                mma_fp16(oacc[nt], a, b);
            }
        }

#pragma unroll
        for (int nt = 0; nt < 4; nt++) {
            const int col = c * 128 + warp_n2 + nt * 8 + 2 * lq;
            __half2 h0 = __floats2half2_rn(oacc[nt][0], oacc[nt][1]);
            __half2 h1 = __floats2half2_rn(oacc[nt][2], oacc[nt][3]);
            *reinterpret_cast<uint32_t*>(oh + (size_t)(m0 + r0) * DM + col) =
                *reinterpret_cast<uint32_t*>(&h0);
            *reinterpret_cast<uint32_t*>(oh + (size_t)(m0 + r1) * DM + col) =
                *reinterpret_cast<uint32_t*>(&h1);
        }
        __syncthreads();
        if (c + 2 < 4) issue_v(c + 2, stg[c & 1]);
    }
}

// ---------------------------------------------------------------------------
extern "C" void kernel_launch(void* const* d_in, const int* in_sizes, int n_in,
                              void* d_out, int out_size)
{
    const float* x      = (const float*)d_in[0];
    const float* w_qkv  = (const float*)d_in[1];
    const float* b_qkv  = (const float*)d_in[2];
    const float* w_proj = (const float*)d_in[3];
    const float* b_proj = (const float*)d_in[4];
    float* out = (float*)d_out;

    __half *qkvh, *xh, *wqh, *wph, *ah;
    cudaGetSymbolAddress((void**)&qkvh, g_qkvh);
    cudaGetSymbolAddress((void**)&xh,  g_xh);
    cudaGetSymbolAddress((void**)&wqh, g_wqh);
    cudaGetSymbolAddress((void**)&wph, g_wph);
    cudaGetSymbolAddress((void**)&ah,  g_ah);

    static bool attr_set = false;
    if (!attr_set) {
        cudaFuncSetAttribute((const void*)gemm_fp16<8, 1>,
                             cudaFuncAttributeMaxDynamicSharedMemorySize, GEMM_SMEM);
        cudaFuncSetAttribute((const void*)gemm_fp16<16, 0>,
                             cudaFuncAttributeMaxDynamicSharedMemorySize, GEMM_SMEM);
        cudaFuncSetAttribute((const void*)attn_mma,
                             cudaFuncAttributeMaxDynamicSharedMemorySize, ATTN_SMEM);
        attr_set = true;
    }

    // 0) fused fp16 converts (one launch)
    const int n0 = NROWS * DM / 4, n1 = QKV_N * DM / 4, n2 = DM * DM / 4;
    conv_fp16_3<<<(n0 + n1 + n2 + 255) / 256, 256>>>(
        (const float4*)x, xh, n0,
        (const float4*)w_qkv, wqh, n1,
        (const float4*)w_proj, wph, n2);

    // 1) qkv = x @ w_qkv^T + b_qkv   [4096,1536], fp16 out  (384 CTAs, 8 warps)
    gemm_fp16<8, 1><<<dim3(QKV_N / 128, NROWS / 128), 256, GEMM_SMEM>>>(
        QKV_N, DM / 64, xh, wqh, b_qkv, qkvh);

    // 2) pipelined tensor-core local attention
    attn_mma<<<NROWS / TQ, 256, ATTN_SMEM>>>(qkvh, ah);

    // 3) out = att @ w_proj^T + b_proj  (fp32 out, 128 CTAs, 16 warps)
    gemm_fp16<16, 0><<<dim3(DM / 128, NROWS / 128), 512, GEMM_SMEM>>>(
        DM, DM / 64, ah, wph, b_proj, out);
}